// round 12
// baseline (speedup 1.0000x reference)
#include <cuda_runtime.h>
#include <cuda_bf16.h>

#define N_NODES 100000
#define N_EDGES 1600000
#define IN_F    128
#define HEADS   4
#define HF      64
#define NEG_SLOPE 0.2f
#define CAP     64          // per-node slot capacity (Poisson(16): P(deg>=64)~2e-18)

// Scratch (__device__ globals; zero-initialized at module load)
__device__ float g_z[N_NODES * HF];          // 25.6 MB projected features
__device__ float g_el[N_NODES * HEADS];
__device__ float g_er[N_NODES * HEADS];
__device__ int   g_cnt[N_NODES];             // INVARIANT: zero at kernel_launch entry
__device__ int   g_slot[N_NODES * CAP];      // 25.6 MB: src ids, CAP slots per dst

// Host-side fork/join plumbing (created once; identical DAG captured per call)
static cudaStream_t g_side;
static cudaEvent_t  g_ev_fork, g_ev_join;
static struct _HostInit {
    _HostInit() {
        cudaStreamCreateWithFlags(&g_side, cudaStreamNonBlocking);
        cudaEventCreateWithFlags(&g_ev_fork, cudaEventDisableTiming);
        cudaEventCreateWithFlags(&g_ev_join, cudaEventDisableTiming);
    }
} g_host_init;

__device__ __forceinline__ float lrelu(float x) {
    return x > 0.0f ? x : NEG_SLOPE * x;
}

// --- packed f32x2 helpers (sm_103a FFMA2; ptxas won't auto-fuse) -----------
__device__ __forceinline__ unsigned long long pack2(float a, float b) {
    unsigned long long r;
    asm("mov.b64 %0, {%1, %2};" : "=l"(r) : "f"(a), "f"(b));
    return r;
}
__device__ __forceinline__ void ffma2(unsigned long long& d,
                                      unsigned long long a,
                                      unsigned long long b) {
    asm("fma.rn.f32x2 %0, %1, %2, %0;" : "+l"(d) : "l"(a), "l"(b));
}
__device__ __forceinline__ float2 unpack2(unsigned long long v) {
    float lo, hi;
    asm("mov.b64 {%0, %1}, %2;" : "=f"(lo), "=f"(hi) : "l"(v));
    return make_float2(lo, hi);
}

// ---------------------------------------------------------------------------
// GEMM: z = feats @ W^T, el/er = <z, attn>.
// 64 nodes/block, 256 threads, 4x4 register tile, FFMA2 inner loop.
// ---------------------------------------------------------------------------
__global__ __launch_bounds__(256) void k_gemm(const float* __restrict__ feats,
                                              const float* __restrict__ W,
                                              const float* __restrict__ attn_l,
                                              const float* __restrict__ attn_r) {
    __shared__ float fsmT[64][68];   // [k][node], padded
    __shared__ float Wsm[64][68];    // [k][col]

    int tid = threadIdx.x;
    int bn = blockIdx.x * 64;
    int ng = tid >> 4;      // 0..15 -> 4 nodes
    int cg = tid & 15;      // 0..15 -> 4 cols

    unsigned long long acc2[4][2];   // [node][col-pair]
#pragma unroll
    for (int i = 0; i < 4; i++) { acc2[i][0] = 0ull; acc2[i][1] = 0ull; }

#pragma unroll
    for (int p = 0; p < 2; p++) {
        int k0 = p * 64;
        if (p) __syncthreads();
#pragma unroll
        for (int idx = tid; idx < 4096; idx += 256) {
            int node = idx >> 6;
            int kk   = idx & 63;
            float v = 0.0f;
            if (bn + node < N_NODES) v = feats[(bn + node) * IN_F + k0 + kk];
            fsmT[kk][node] = v;
        }
#pragma unroll
        for (int idx = tid; idx < 4096; idx += 256) {
            int col = idx >> 6;
            int kk  = idx & 63;
            Wsm[kk][col] = W[col * IN_F + k0 + kk];
        }
        __syncthreads();

#pragma unroll 8
        for (int kk = 0; kk < 64; kk++) {
            float4 f4 = *(const float4*)&fsmT[kk][ng * 4];
            float4 w4 = *(const float4*)&Wsm[kk][cg * 4];
            unsigned long long wA = pack2(w4.x, w4.y);
            unsigned long long wB = pack2(w4.z, w4.w);
            unsigned long long b0 = pack2(f4.x, f4.x);
            unsigned long long b1 = pack2(f4.y, f4.y);
            unsigned long long b2 = pack2(f4.z, f4.z);
            unsigned long long b3 = pack2(f4.w, f4.w);
            ffma2(acc2[0][0], b0, wA); ffma2(acc2[0][1], b0, wB);
            ffma2(acc2[1][0], b1, wA); ffma2(acc2[1][1], b1, wB);
            ffma2(acc2[2][0], b2, wA); ffma2(acc2[2][1], b2, wB);
            ffma2(acc2[3][0], b3, wA); ffma2(acc2[3][1], b3, wB);
        }
    }

    // epilogue
    int h = cg >> 2;
    float al[4], ar[4];
#pragma unroll
    for (int j = 0; j < 4; j++) {
        al[j] = attn_l[cg * 4 + j];
        ar[j] = attn_r[cg * 4 + j];
    }
#pragma unroll
    for (int i = 0; i < 4; i++) {
        int node = bn + ng * 4 + i;
        float2 a01 = unpack2(acc2[i][0]);
        float2 a23 = unpack2(acc2[i][1]);
        float acc0 = a01.x, acc1 = a01.y, acc2f = a23.x, acc3 = a23.y;
        float vl = acc0 * al[0] + acc1 * al[1] + acc2f * al[2] + acc3 * al[3];
        float vr = acc0 * ar[0] + acc1 * ar[1] + acc2f * ar[2] + acc3 * ar[3];
        vl += __shfl_xor_sync(0xffffffffu, vl, 1);
        vl += __shfl_xor_sync(0xffffffffu, vl, 2);
        vr += __shfl_xor_sync(0xffffffffu, vr, 1);
        vr += __shfl_xor_sync(0xffffffffu, vr, 2);
        if (node < N_NODES) {
            *(float4*)&g_z[node * HF + cg * 4] = make_float4(acc0, acc1, acc2f, acc3);
            if ((cg & 3) == 0) {
                g_el[node * HEADS + h] = vl;
                g_er[node * HEADS + h] = vr;
            }
        }
    }
}

// ---------------------------------------------------------------------------
// Scatter (bump allocator): the ENTIRE CSR build. 1 edge/thread.
// pos = cursor++ within dst's fixed 64-slot region. Requires g_cnt == 0.
// ---------------------------------------------------------------------------
__global__ void k_scatter(const int* __restrict__ src, const int* __restrict__ dst) {
    int e = blockIdx.x * blockDim.x + threadIdx.x;
    if (e >= N_EDGES) return;
    int s = src[e];
    int d = dst[e];
    int pos = atomicAdd(&g_cnt[d], 1);
    if (pos < CAP) g_slot[d * CAP + pos] = s;   // guard: never triggers for this data
}

// ---------------------------------------------------------------------------
// Aggregate: one warp per dst node; half-warp edge streams (R9 proven),
// lane covers 4 cols via float4; 2-deep prefetch. shfl_xor(16) merges.
// Reads count from g_cnt and resets it to 0 (restores invariant).
// ---------------------------------------------------------------------------
__global__ __launch_bounds__(256) void k_agg(const float* __restrict__ bias,
                                             float* __restrict__ out) {
    int gwarp = (blockIdx.x * blockDim.x + threadIdx.x) >> 5;
    int lane  = threadIdx.x & 31;
    if (gwarp >= N_NODES) return;
    int d  = gwarp;
    int hw = lane >> 4;        // half-warp: which edge stream (even/odd)
    int l  = lane & 15;        // col group: floats [4l, 4l+4)
    int h  = l >> 2;           // head for these cols

    int n = g_cnt[d];          // broadcast load (all lanes, same address)
    if (lane == 0) g_cnt[d] = 0;   // restore invariant for next call
    if (n > CAP) n = CAP;

    float er_h = g_er[d * HEADS + h];

    int beg = d * CAP;
    int end = beg + n;

    float4 num = make_float4(0.0f, 0.0f, 0.0f, 0.0f);
    float  den = 0.0f;

    int i = beg + hw;          // this half-warp's stream: beg+hw, +2, +4, ...
    int   sA = 0;
    float elA = 0.0f;
    if (i < end) { sA = g_slot[i]; elA = g_el[sA * HEADS + h]; }

    while (i < end) {
        float4 zv = *(const float4*)&g_z[sA * HF + 4 * l];
        float ex = __expf(lrelu(elA + er_h));
        int inext = i + 2;
        if (inext < end) { sA = g_slot[inext]; elA = g_el[sA * HEADS + h]; }
        num.x = fmaf(ex, zv.x, num.x);
        num.y = fmaf(ex, zv.y, num.y);
        num.z = fmaf(ex, zv.z, num.z);
        num.w = fmaf(ex, zv.w, num.w);
        den += ex;
        i = inext;
    }

    // merge the two half-warp streams
    num.x += __shfl_xor_sync(0xffffffffu, num.x, 16);
    num.y += __shfl_xor_sync(0xffffffffu, num.y, 16);
    num.z += __shfl_xor_sync(0xffffffffu, num.z, 16);
    num.w += __shfl_xor_sync(0xffffffffu, num.w, 16);
    den   += __shfl_xor_sync(0xffffffffu, den,   16);

    if (hw == 0) {
        float inv = (den > 0.0f) ? __frcp_rn(den) : 0.0f;   // empty -> bias
        const float4 b4 = *(const float4*)&bias[4 * l];
        float4 o;
        o.x = num.x * inv + b4.x;
        o.y = num.y * inv + b4.y;
        o.z = num.z * inv + b4.z;
        o.w = num.w * inv + b4.w;
        *(float4*)&out[d * HF + 4 * l] = o;
    }
}

// ---------------------------------------------------------------------------
// Launch DAG:
//   main:  [fork] -> k_gemm ----------\
//   side:  [fork] -> k_scatter -> [join] -> k_agg (main)
// ---------------------------------------------------------------------------
extern "C" void kernel_launch(void* const* d_in, const int* in_sizes, int n_in,
                              void* d_out, int out_size) {
    const float* feats  = (const float*)d_in[0];
    const float* W      = (const float*)d_in[1];
    const float* attn_l = (const float*)d_in[2];
    const float* attn_r = (const float*)d_in[3];
    const float* bias   = (const float*)d_in[4];
    const int*   src    = (const int*)d_in[5];
    const int*   dst    = (const int*)d_in[6];
    float* out = (float*)d_out;

    (void)in_sizes; (void)n_in; (void)out_size;

    // fork side stream off the (possibly capturing) default stream
    cudaEventRecord(g_ev_fork, 0);
    cudaStreamWaitEvent(g_side, g_ev_fork, 0);

    // chain A (default stream): projection
    k_gemm<<<(N_NODES + 63) / 64, 256>>>(feats, W, attn_l, attn_r);

    // chain B (side stream): bump-allocator CSR build — independent of gemm
    k_scatter<<<(N_EDGES + 255) / 256, 256, 0, g_side>>>(src, dst);

    // join
    cudaEventRecord(g_ev_join, g_side);
    cudaStreamWaitEvent(0, g_ev_join, 0);

    k_agg<<<(N_NODES + 7) / 8, 256>>>(bias, out);
}

// round 13
// speedup vs baseline: 2.3788x; 2.3788x over previous
#include <cuda_runtime.h>
#include <cuda_bf16.h>

#define N_NODES 100000
#define N_EDGES 1600000
#define IN_F    128
#define HEADS   4
#define HF      64
#define NEG_SLOPE 0.2f
#define NB_SCAN 98          // ceil(N_NODES / 1024)

// Scratch (__device__ globals; zero-initialized at module load)
__device__ float g_z[N_NODES * HF];          // 25.6 MB projected features
__device__ float g_el[N_NODES * HEADS];
__device__ float g_er[N_NODES * HEADS];
__device__ int   g_cnt[N_NODES];             // INVARIANT: zero at kernel_launch entry
__device__ int   g_off[N_NODES + 1];         // CSR offsets by dst
__device__ int   g_bsum[128];
__device__ int   g_srt_src[N_EDGES];         // src per edge, grouped by dst

// Host-side fork/join plumbing (created once; identical DAG captured per call)
static cudaStream_t g_side;
static cudaEvent_t  g_ev_fork, g_ev_join;
static struct _HostInit {
    _HostInit() {
        cudaStreamCreateWithFlags(&g_side, cudaStreamNonBlocking);
        cudaEventCreateWithFlags(&g_ev_fork, cudaEventDisableTiming);
        cudaEventCreateWithFlags(&g_ev_join, cudaEventDisableTiming);
    }
} g_host_init;

__device__ __forceinline__ float lrelu(float x) {
    return x > 0.0f ? x : NEG_SLOPE * x;
}

// --- packed f32x2 helpers (sm_103a FFMA2; ptxas won't auto-fuse) -----------
__device__ __forceinline__ unsigned long long pack2(float a, float b) {
    unsigned long long r;
    asm("mov.b64 %0, {%1, %2};" : "=l"(r) : "f"(a), "f"(b));
    return r;
}
__device__ __forceinline__ void ffma2(unsigned long long& d,
                                      unsigned long long a,
                                      unsigned long long b) {
    asm("fma.rn.f32x2 %0, %1, %2, %0;" : "+l"(d) : "l"(a), "l"(b));
}
__device__ __forceinline__ float2 unpack2(unsigned long long v) {
    float lo, hi;
    asm("mov.b64 {%0, %1}, %2;" : "=f"(lo), "=f"(hi) : "l"(v));
    return make_float2(lo, hi);
}

// ---------------------------------------------------------------------------
// GEMM: z = feats @ W^T, el/er = <z, attn>.
// 64 nodes/block, 256 threads, 4x4 register tile, FFMA2 inner loop.
// feats read with __ldcs (read-once, 51 MB): evict-first so it does NOT
// pollute L2 / evict z, el, er, srt_src that k_agg needs.
// ---------------------------------------------------------------------------
__global__ __launch_bounds__(256) void k_gemm(const float* __restrict__ feats,
                                              const float* __restrict__ W,
                                              const float* __restrict__ attn_l,
                                              const float* __restrict__ attn_r) {
    __shared__ float fsmT[64][68];   // [k][node], padded
    __shared__ float Wsm[64][68];    // [k][col]

    int tid = threadIdx.x;
    int bn = blockIdx.x * 64;
    int ng = tid >> 4;      // 0..15 -> 4 nodes
    int cg = tid & 15;      // 0..15 -> 4 cols

    unsigned long long acc2[4][2];   // [node][col-pair]
#pragma unroll
    for (int i = 0; i < 4; i++) { acc2[i][0] = 0ull; acc2[i][1] = 0ull; }

#pragma unroll
    for (int p = 0; p < 2; p++) {
        int k0 = p * 64;
        if (p) __syncthreads();
#pragma unroll
        for (int idx = tid; idx < 4096; idx += 256) {
            int node = idx >> 6;
            int kk   = idx & 63;
            float v = 0.0f;
            if (bn + node < N_NODES)
                v = __ldcs(&feats[(bn + node) * IN_F + k0 + kk]);  // streaming
            fsmT[kk][node] = v;
        }
#pragma unroll
        for (int idx = tid; idx < 4096; idx += 256) {
            int col = idx >> 6;
            int kk  = idx & 63;
            Wsm[kk][col] = W[col * IN_F + k0 + kk];
        }
        __syncthreads();

#pragma unroll 8
        for (int kk = 0; kk < 64; kk++) {
            float4 f4 = *(const float4*)&fsmT[kk][ng * 4];
            float4 w4 = *(const float4*)&Wsm[kk][cg * 4];
            unsigned long long wA = pack2(w4.x, w4.y);
            unsigned long long wB = pack2(w4.z, w4.w);
            unsigned long long b0 = pack2(f4.x, f4.x);
            unsigned long long b1 = pack2(f4.y, f4.y);
            unsigned long long b2 = pack2(f4.z, f4.z);
            unsigned long long b3 = pack2(f4.w, f4.w);
            ffma2(acc2[0][0], b0, wA); ffma2(acc2[0][1], b0, wB);
            ffma2(acc2[1][0], b1, wA); ffma2(acc2[1][1], b1, wB);
            ffma2(acc2[2][0], b2, wA); ffma2(acc2[2][1], b2, wB);
            ffma2(acc2[3][0], b3, wA); ffma2(acc2[3][1], b3, wB);
        }
    }

    // epilogue
    int h = cg >> 2;
    float al[4], ar[4];
#pragma unroll
    for (int j = 0; j < 4; j++) {
        al[j] = attn_l[cg * 4 + j];
        ar[j] = attn_r[cg * 4 + j];
    }
#pragma unroll
    for (int i = 0; i < 4; i++) {
        int node = bn + ng * 4 + i;
        float2 a01 = unpack2(acc2[i][0]);
        float2 a23 = unpack2(acc2[i][1]);
        float acc0 = a01.x, acc1 = a01.y, acc2f = a23.x, acc3 = a23.y;
        float vl = acc0 * al[0] + acc1 * al[1] + acc2f * al[2] + acc3 * al[3];
        float vr = acc0 * ar[0] + acc1 * ar[1] + acc2f * ar[2] + acc3 * ar[3];
        vl += __shfl_xor_sync(0xffffffffu, vl, 1);
        vl += __shfl_xor_sync(0xffffffffu, vl, 2);
        vr += __shfl_xor_sync(0xffffffffu, vr, 1);
        vr += __shfl_xor_sync(0xffffffffu, vr, 2);
        if (node < N_NODES) {
            *(float4*)&g_z[node * HF + cg * 4] = make_float4(acc0, acc1, acc2f, acc3);
            if ((cg & 3) == 0) {
                g_el[node * HEADS + h] = vl;
                g_er[node * HEADS + h] = vr;
            }
        }
    }
}

// ---------------------------------------------------------------------------
// Histogram of dst (4 edges/thread, streaming reads). Requires g_cnt == 0.
// ---------------------------------------------------------------------------
__global__ void k_hist(const int* __restrict__ dst) {
    int t = blockIdx.x * blockDim.x + threadIdx.x;
    int base = t * 4;
    if (base >= N_EDGES) return;
    int4 d4 = __ldcs((const int4*)&dst[base]);   // N_EDGES % 4 == 0
    atomicAdd(&g_cnt[d4.x], 1);
    atomicAdd(&g_cnt[d4.y], 1);
    atomicAdd(&g_cnt[d4.z], 1);
    atomicAdd(&g_cnt[d4.w], 1);
}

// ---------------------------------------------------------------------------
// Scan phase 1: per-block (1024) exclusive scan, block totals to g_bsum
// ---------------------------------------------------------------------------
__global__ __launch_bounds__(1024) void k_scan1() {
    __shared__ int wsum[32];
    int tid  = threadIdx.x;
    int lane = tid & 31;
    int wid  = tid >> 5;
    int i = blockIdx.x * 1024 + tid;
    int v = (i < N_NODES) ? g_cnt[i] : 0;
    int x = v;
#pragma unroll
    for (int o = 1; o < 32; o <<= 1) {
        int y = __shfl_up_sync(0xffffffffu, x, o);
        if (lane >= o) x += y;
    }
    if (lane == 31) wsum[wid] = x;
    __syncthreads();
    if (wid == 0) {
        int wv = wsum[lane];
        int xs = wv;
#pragma unroll
        for (int o = 1; o < 32; o <<= 1) {
            int y = __shfl_up_sync(0xffffffffu, xs, o);
            if (lane >= o) xs += y;
        }
        wsum[lane] = xs - wv;
    }
    __syncthreads();
    int excl = x - v + wsum[wid];
    if (i < N_NODES) g_off[i] = excl;
    if (tid == 1023) g_bsum[blockIdx.x] = excl + v;
}

// ---------------------------------------------------------------------------
// Scan phase 2+3 fused: each block derives its base from g_bsum, adds it,
// initializes cursor.
// ---------------------------------------------------------------------------
__global__ __launch_bounds__(1024) void k_scan3() {
    __shared__ int s_base;
    int tid = threadIdx.x;
    if (tid < 32) {
        int acc = 0;
        for (int j = tid; j < NB_SCAN; j += 32)
            if (j < (int)blockIdx.x) acc += g_bsum[j];
#pragma unroll
        for (int o = 16; o >= 1; o >>= 1)
            acc += __shfl_xor_sync(0xffffffffu, acc, o);
        if (tid == 0) s_base = acc;
    }
    __syncthreads();
    int i = blockIdx.x * 1024 + tid;
    if (i < N_NODES) {
        int o = g_off[i] + s_base;
        g_off[i] = o;
        g_cnt[i] = o;
    }
    if (i == 0) g_off[N_NODES] = N_EDGES;
}

// ---------------------------------------------------------------------------
// Scatter: pure index permutation. 1 edge/thread, streaming index reads.
// ---------------------------------------------------------------------------
__global__ void k_scatter(const int* __restrict__ src, const int* __restrict__ dst) {
    int e = blockIdx.x * blockDim.x + threadIdx.x;
    if (e >= N_EDGES) return;
    int s = __ldcs(&src[e]);
    int d = __ldcs(&dst[e]);
    int pos = atomicAdd(&g_cnt[d], 1);
    g_srt_src[pos] = s;
}

// ---------------------------------------------------------------------------
// Aggregate (R9/R11 proven config): one warp per dst node; half-warp edge
// streams, lane covers 4 cols via float4; 2-deep prefetch per stream.
// shfl_xor(16) merges. Restores g_cnt to 0.
// ---------------------------------------------------------------------------
__global__ __launch_bounds__(256) void k_agg(const float* __restrict__ bias,
                                             float* __restrict__ out) {
    int gwarp = (blockIdx.x * blockDim.x + threadIdx.x) >> 5;
    int lane  = threadIdx.x & 31;
    if (gwarp >= N_NODES) return;
    int d  = gwarp;
    int hw = lane >> 4;        // half-warp: which edge stream (even/odd)
    int l  = lane & 15;        // col group: floats [4l, 4l+4)
    int h  = l >> 2;           // head for these cols

    if (lane == 0) g_cnt[d] = 0;   // restore invariant for histogram

    float er_h = g_er[d * HEADS + h];

    int beg = g_off[d];
    int end = g_off[d + 1];

    float4 num = make_float4(0.0f, 0.0f, 0.0f, 0.0f);
    float  den = 0.0f;

    int i = beg + hw;          // this half-warp's stream: beg+hw, +2, +4, ...
    int   sA = 0;
    float elA = 0.0f;
    if (i < end) { sA = g_srt_src[i]; elA = g_el[sA * HEADS + h]; }

    while (i < end) {
        float4 zv = *(const float4*)&g_z[sA * HF + 4 * l];
        float ex = __expf(lrelu(elA + er_h));
        int inext = i + 2;
        if (inext < end) { sA = g_srt_src[inext]; elA = g_el[sA * HEADS + h]; }
        num.x = fmaf(ex, zv.x, num.x);
        num.y = fmaf(ex, zv.y, num.y);
        num.z = fmaf(ex, zv.z, num.z);
        num.w = fmaf(ex, zv.w, num.w);
        den += ex;
        i = inext;
    }

    // merge the two half-warp streams
    num.x += __shfl_xor_sync(0xffffffffu, num.x, 16);
    num.y += __shfl_xor_sync(0xffffffffu, num.y, 16);
    num.z += __shfl_xor_sync(0xffffffffu, num.z, 16);
    num.w += __shfl_xor_sync(0xffffffffu, num.w, 16);
    den   += __shfl_xor_sync(0xffffffffu, den,   16);

    if (hw == 0) {
        float inv = (den > 0.0f) ? __frcp_rn(den) : 0.0f;   // empty -> bias
        const float4 b4 = *(const float4*)&bias[4 * l];
        float4 o;
        o.x = num.x * inv + b4.x;
        o.y = num.y * inv + b4.y;
        o.z = num.z * inv + b4.z;
        o.w = num.w * inv + b4.w;
        *(float4*)&out[d * HF + 4 * l] = o;
    }
}

// ---------------------------------------------------------------------------
// Launch DAG:
//   main:  [fork] -> k_gemm ------------------\
//   side:  [fork] -> k_hist -> scans -> scatter -> [join] -> k_agg (main)
// ---------------------------------------------------------------------------
extern "C" void kernel_launch(void* const* d_in, const int* in_sizes, int n_in,
                              void* d_out, int out_size) {
    const float* feats  = (const float*)d_in[0];
    const float* W      = (const float*)d_in[1];
    const float* attn_l = (const float*)d_in[2];
    const float* attn_r = (const float*)d_in[3];
    const float* bias   = (const float*)d_in[4];
    const int*   src    = (const int*)d_in[5];
    const int*   dst    = (const int*)d_in[6];
    float* out = (float*)d_out;

    (void)in_sizes; (void)n_in; (void)out_size;

    // fork side stream off the (possibly capturing) default stream
    cudaEventRecord(g_ev_fork, 0);
    cudaStreamWaitEvent(g_side, g_ev_fork, 0);

    // chain A (default stream): projection
    k_gemm<<<(N_NODES + 63) / 64, 256>>>(feats, W, attn_l, attn_r);

    // chain B (side stream): CSR build — independent of gemm
    k_hist<<<(N_EDGES / 4 + 255) / 256, 256, 0, g_side>>>(dst);
    k_scan1<<<NB_SCAN, 1024, 0, g_side>>>();
    k_scan3<<<NB_SCAN, 1024, 0, g_side>>>();
    k_scatter<<<(N_EDGES + 255) / 256, 256, 0, g_side>>>(src, dst);

    // join
    cudaEventRecord(g_ev_join, g_side);
    cudaStreamWaitEvent(0, g_ev_join, 0);

    k_agg<<<(N_NODES + 7) / 8, 256>>>(bias, out);
}